// round 10
// baseline (speedup 1.0000x reference)
#include <cuda_runtime.h>
#include <cstdint>

#define SDIM 1024
#define BHN  64
#define THREADS 256
#define SLOT_BYTES 32768              /* A: 16KB (128x32 f32) + B: 16KB (32x128) */
#define STAGES 3
#define SMEM_BYTES (STAGES * SLOT_BYTES)   /* 96KB */

// Scratch: attention probs + tf32-converted operand copies.
__device__ __align__(16) float g_attn[(size_t)BHN * SDIM * SDIM];
__device__ __align__(16) float g_cvt0[(size_t)BHN * SDIM * SDIM];  // A, later P
__device__ __align__(16) float g_cvt1[(size_t)BHN * SDIM * SDIM];  // J

__device__ __forceinline__ uint32_t f2tf(float x) {
    uint32_t r;
    asm("cvt.rna.tf32.f32 %0, %1;" : "=r"(r) : "f"(x));
    return r;
}

__device__ __forceinline__ uint32_t smem_u32(const void* p) {
    uint32_t a;
    asm("{ .reg .u64 t; cvta.to.shared.u64 t, %1; cvt.u32.u64 %0, t; }"
        : "=r"(a) : "l"(p));
    return a;
}

__device__ __forceinline__ void cp16(uint32_t smem_dst, const void* gmem_src) {
    asm volatile("cp.async.cg.shared.global [%0], [%1], 16;"
                 :: "r"(smem_dst), "l"(gmem_src) : "memory");
}

__device__ __forceinline__ void cp_commit() {
    asm volatile("cp.async.commit_group;" ::: "memory");
}

__device__ __forceinline__ void cp_wait1() {
    asm volatile("cp.async.wait_group 1;" ::: "memory");
}

__device__ __forceinline__ void ldsm4(uint32_t a[4], uint32_t addr) {
    asm volatile("ldmatrix.sync.aligned.m8n8.x4.shared.b16 {%0,%1,%2,%3}, [%4];"
        : "=r"(a[0]), "=r"(a[1]), "=r"(a[2]), "=r"(a[3]) : "r"(addr));
}

__device__ __forceinline__ uint32_t lds32(uint32_t addr) {
    uint32_t v;
    asm volatile("ld.shared.b32 %0, [%1];" : "=r"(v) : "r"(addr));
    return v;
}

__device__ __forceinline__ void mma_tf32(float c[4], const uint32_t a[4],
                                         uint32_t b0, uint32_t b1) {
    asm volatile(
        "mma.sync.aligned.m16n8k8.row.col.f32.tf32.tf32.f32 "
        "{%0,%1,%2,%3}, {%4,%5,%6,%7}, {%8,%9}, {%0,%1,%2,%3};"
        : "+f"(c[0]), "+f"(c[1]), "+f"(c[2]), "+f"(c[3])
        : "r"(a[0]), "r"(a[1]), "r"(a[2]), "r"(a[3]), "r"(b0), "r"(b1));
}

// Elementwise tf32 rounding pass: dst = tf32(src). BW-bound.
__global__ __launch_bounds__(256) void cvt_kernel(
    const float4* __restrict__ src, float4* __restrict__ dst)
{
    size_t i0 = (size_t)blockIdx.x * 2048 + threadIdx.x;
    #pragma unroll
    for (int i = 0; i < 8; ++i) {
        float4 v = src[i0 + i * 256];
        uint4 u;
        u.x = f2tf(v.x); u.y = f2tf(v.y); u.z = f2tf(v.z); u.w = f2tf(v.w);
        *reinterpret_cast<uint4*>(&dst[i0 + i * 256]) = u;
    }
}

// CTA tile 128x128, 8 warps (2x4), warp tile 64x32, mma m16n8k8 tf32.
// Operands are PRE-ROUNDED to tf32 in global memory -> no cvt in the hot loop.
// 3-stage cp.async ring, single __syncthreads per mainloop iteration.
// A smem: [m][32w] 128B rows, 16B-chunk swizzle ch^(m&7)  -> ldmatrix.x4 reads.
// B smem: [k][128w] 512B rows, word swizzle n^((k&7)<<3)  -> conflict-free LDS.32.
// fuse_epi=1: out = (acc + AddM)*scale + Mask  (QK -> g_attn); 0: out = acc.
__global__ __launch_bounds__(THREADS, 2) void gemm_kernel(
    const float* __restrict__ Ag, const float* __restrict__ Bg,
    const float* __restrict__ AddM, const float* __restrict__ Mask,
    float* __restrict__ Out, int fuse_epi)
{
    extern __shared__ __align__(128) char smem[];
    const uint32_t sbase = smem_u32(smem);

    const int bm = blockIdx.x, bn = blockIdx.y, bh = blockIdx.z;
    const int tid  = threadIdx.x;
    const int warp = tid >> 5, lane = tid & 31;
    const int wm = warp >> 2, wn = warp & 3;   // 2 x 4 warp grid
    const int lr = lane >> 2, lc = lane & 3;

    const size_t mat = (size_t)bh * SDIM * SDIM;
    const float* Abase = Ag + mat + (size_t)(bm * 128) * SDIM;
    const float* Bbase = Bg + mat + bn * 128;

    float c[4][4][4];
    #pragma unroll
    for (int i = 0; i < 4; i++)
        #pragma unroll
        for (int j = 0; j < 4; j++)
            #pragma unroll
            for (int r = 0; r < 4; r++) c[i][j][r] = 0.f;

    // A fragment geometry (ldmatrix), verified rounds 3/5-8.
    const int moff = ((lane >> 3) & 1) * 8 + (lane & 7);
    const int csel = lane >> 4;
    uint32_t a_base[4];
    int      a_m7[4];
    #pragma unroll
    for (int ti = 0; ti < 4; ti++) {
        int m = wm * 64 + ti * 16 + moff;
        a_base[ti] = (uint32_t)m * 128u;
        a_m7[ti]   = m & 7;
    }
    // B fragment geometry: lane holds n = wn*32 + tj*8 + lr, k = kk + lc (+4).
    uint32_t nxb[4];
    #pragma unroll
    for (int tj = 0; tj < 4; tj++) {
        int n = wn * 32 + tj * 8 + lr;
        nxb[tj] = (uint32_t)((n ^ (lc << 3)) << 2);
    }

    // Per-thread fill coordinates (256 threads: 4 x 16B each for A and B).
    const int fa_r  = tid >> 3;
    const int fa_ch = tid & 7;
    const int fb_k  = tid >> 5;
    const int fb_nq = (tid & 31) << 2;
    uint32_t a_dst[4], b_dst[4];
    const float* a_src[4];
    const float* b_src[4];
    #pragma unroll
    for (int i = 0; i < 4; i++) {
        int r = fa_r + i * 32;
        a_dst[i] = (uint32_t)(r * 128 + ((fa_ch ^ (r & 7)) << 4));
        a_src[i] = Abase + (size_t)r * SDIM + fa_ch * 4;
        int k = fb_k + i * 8;
        b_dst[i] = (uint32_t)(16384 + k * 512 + ((fb_nq ^ ((k & 7) << 3)) << 2));
        b_src[i] = Bbase + (size_t)k * SDIM + fb_nq;
    }

    auto fill = [&](int stage, int kt) {
        const uint32_t s0 = sbase + stage * SLOT_BYTES;
        #pragma unroll
        for (int i = 0; i < 4; ++i) cp16(s0 + a_dst[i], a_src[i] + kt);
        #pragma unroll
        for (int i = 0; i < 4; ++i) cp16(s0 + b_dst[i], b_src[i] + (size_t)kt * SDIM);
    };

    auto compute = [&](int stage) {
        const uint32_t sA = sbase + stage * SLOT_BYTES;
        const uint32_t sB = sA + 16384;
        #pragma unroll
        for (int kk4 = 0; kk4 < 4; ++kk4) {
            uint32_t af[4][4];
            const int chunk = (kk4 << 1) + csel;
            #pragma unroll
            for (int ti = 0; ti < 4; ++ti)
                ldsm4(af[ti], sA + a_base[ti] + (uint32_t)((chunk ^ a_m7[ti]) << 4));

            uint32_t b0[4], b1[4];
            const uint32_t row0 = sB + (uint32_t)((kk4 << 3) + lc) * 512u;
            const uint32_t row1 = row0 + 2048u;
            #pragma unroll
            for (int tj = 0; tj < 4; ++tj) {
                b0[tj] = lds32(row0 + nxb[tj]);
                b1[tj] = lds32(row1 + (nxb[tj] ^ 128u));
            }
            #pragma unroll
            for (int ti = 0; ti < 4; ++ti)
                #pragma unroll
                for (int tj = 0; tj < 4; ++tj)
                    mma_tf32(c[ti][tj], af[ti], b0[tj], b1[tj]);
        }
    };

    // Prologue: STAGES-1 tiles in flight.
    fill(0, 0);  cp_commit();
    fill(1, 32); cp_commit();

    #pragma unroll 1
    for (int it = 0; it < 32; ++it) {
        const int stage = it % STAGES;
        cp_wait1();          // tile `it` arrived (this thread's groups)
        __syncthreads();     // publish arrivals + fence WAR on stage (it-1)%3
        compute(stage);
        if (it + 2 < 32) fill((it + 2) % STAGES, (it + 2) << 5);
        cp_commit();         // uniform group accounting (empty groups at tail)
    }

    // ---- epilogue ----
    const float scale = 0.03125f;  // 1/sqrt(1024)
    #pragma unroll
    for (int ti = 0; ti < 4; ti++) {
        #pragma unroll
        for (int tj = 0; tj < 4; tj++) {
            int i0 = bm * 128 + wm * 64 + ti * 16 + lr;
            int j0 = bn * 128 + wn * 32 + tj * 8 + lc * 2;
            #pragma unroll
            for (int h = 0; h < 2; h++) {
                int i = i0 + h * 8;
                float v0 = c[ti][tj][h * 2 + 0];
                float v1 = c[ti][tj][h * 2 + 1];
                size_t off = mat + (size_t)i * SDIM + j0;
                if (fuse_epi) {
                    float2 bb = *reinterpret_cast<const float2*>(AddM + off);
                    float2 mm = *reinterpret_cast<const float2*>(
                        Mask + (size_t)i * SDIM + j0);
                    v0 = (v0 + bb.x) * scale + mm.x;
                    v1 = (v1 + bb.y) * scale + mm.y;
                }
                float2 o; o.x = v0; o.y = v1;
                *reinterpret_cast<float2*>(Out + off) = o;
            }
        }
    }
}

// One CTA (256 threads) per row; in-place softmax, tf32-rounded output.
__global__ __launch_bounds__(256) void softmax_kernel() {
    const size_t row = blockIdx.x;
    float* p = g_attn + row * SDIM;
    const int tid = threadIdx.x;
    const int warp = tid >> 5, lane = tid & 31;
    __shared__ float sred[8];

    float4 v = reinterpret_cast<float4*>(p)[tid];

    float m = fmaxf(fmaxf(v.x, v.y), fmaxf(v.z, v.w));
    #pragma unroll
    for (int o = 16; o; o >>= 1) m = fmaxf(m, __shfl_xor_sync(0xffffffffu, m, o));
    if (lane == 0) sred[warp] = m;
    __syncthreads();
    m = sred[0];
    #pragma unroll
    for (int i = 1; i < 8; i++) m = fmaxf(m, sred[i]);
    __syncthreads();

    v.x = expf(v.x - m);
    v.y = expf(v.y - m);
    v.z = expf(v.z - m);
    v.w = expf(v.w - m);
    float s = v.x + v.y + v.z + v.w;
    #pragma unroll
    for (int o = 16; o; o >>= 1) s += __shfl_xor_sync(0xffffffffu, s, o);
    if (lane == 0) sred[warp] = s;
    __syncthreads();
    s = sred[0];
    #pragma unroll
    for (int i = 1; i < 8; i++) s += sred[i];

    float inv = 1.0f / s;
    v.x = __uint_as_float(f2tf(v.x * inv));
    v.y = __uint_as_float(f2tf(v.y * inv));
    v.z = __uint_as_float(f2tf(v.z * inv));
    v.w = __uint_as_float(f2tf(v.w * inv));
    reinterpret_cast<float4*>(p)[tid] = v;
}

extern "C" void kernel_launch(void* const* d_in, const int* in_sizes, int n_in,
                              void* d_out, int out_size) {
    const float* A    = (const float*)d_in[0];
    const float* J    = (const float*)d_in[1];
    const float* B    = (const float*)d_in[2];
    const float* P    = (const float*)d_in[3];
    const float* mask = (const float*)d_in[4];
    float* out = (float*)d_out;

    float *attn = nullptr, *c0 = nullptr, *c1 = nullptr;
    cudaGetSymbolAddress((void**)&attn, g_attn);
    cudaGetSymbolAddress((void**)&c0, g_cvt0);
    cudaGetSymbolAddress((void**)&c1, g_cvt1);

    cudaFuncSetAttribute(gemm_kernel, cudaFuncAttributeMaxDynamicSharedMemorySize,
                         SMEM_BYTES);

    const int cvt_blocks = (int)(((size_t)BHN * SDIM * SDIM / 4) / 2048);
    dim3 grid(SDIM / 128, SDIM / 128, BHN);  // 8 x 8 x 64

    cvt_kernel<<<cvt_blocks, 256>>>((const float4*)A, (float4*)c0);
    cvt_kernel<<<cvt_blocks, 256>>>((const float4*)J, (float4*)c1);
    gemm_kernel<<<grid, THREADS, SMEM_BYTES>>>(c0, c1, B, mask, attn, 1);
    cvt_kernel<<<cvt_blocks, 256>>>((const float4*)P, (float4*)c0);
    softmax_kernel<<<BHN * SDIM, 256>>>();
    gemm_kernel<<<grid, THREADS, SMEM_BYTES>>>(attn, c0, nullptr, nullptr, out, 0);
}